// round 6
// baseline (speedup 1.0000x reference)
#include <cuda_runtime.h>

#define N_ATOMS 25000
#define N_EDGES 1000000
// moments per atom: 5 radial * 20 unique (1 + 3 + 6 + 10)
#define MOM_PER_ATOM 100

__device__ float g_mom[N_ATOMS * MOM_PER_ATOM];

// tril2 pairs (r>=s), order: for r in 0..4 for s in 0..r
static __device__ const int c_T2I[15] = {0,1,1,2,2,2,3,3,3,3,4,4,4,4,4};
static __device__ const int c_T2J[15] = {0,0,1,0,1,2,0,1,2,3,0,1,2,3,4};
// tril3 triples (r>=s>=t)
static __device__ const int c_T3I[35] = {0, 1,1,1, 2,2,2,2,2,2, 3,3,3,3,3,3,3,3,3,3,
                                         4,4,4,4,4,4,4,4,4,4,4,4,4,4,4};
static __device__ const int c_T3J[35] = {0, 0,1,1, 0,1,1,2,2,2, 0,1,1,2,2,2,3,3,3,3,
                                         0,1,1,2,2,2,3,3,3,3,4,4,4,4,4};
static __device__ const int c_T3K[35] = {0, 0,0,1, 0,0,1,0,1,2, 0,0,1,0,1,2,0,1,2,3,
                                         0,0,1,0,1,2,0,1,2,3,0,1,2,3,4};
// full (i,j) -> unique symmetric index (pairs ordered 00,01,02,11,12,22)
static __device__ const int c_F2U[9]  = {0,1,2, 1,3,4, 2,4,5};
// full (i,j,k) -> unique (triples ordered 000,001,002,011,012,022,111,112,122,222)
static __device__ const int c_F3U[27] = {0,1,2, 1,3,4, 2,4,5,
                                         1,3,4, 3,6,7, 4,7,8,
                                         2,4,5, 4,7,8, 5,8,9};

__global__ void zero_kernel() {
    int t = blockIdx.x * blockDim.x + threadIdx.x;
    if (t < N_ATOMS * MOM_PER_ATOM) g_mom[t] = 0.0f;
}

__global__ void __launch_bounds__(256) edge_kernel(
    const float* __restrict__ dr_vec,
    const int*   __restrict__ Z,
    const int*   __restrict__ nbr,
    const float* __restrict__ coeffs)
{
    int e = blockIdx.x * blockDim.x + threadIdx.x;
    if (e >= N_EDGES) return;

    float x = dr_vec[3*e + 0];
    float y = dr_vec[3*e + 1];
    float z = dr_vec[3*e + 2];
    float dr = sqrtf(x*x + y*y + z*z);
    // cutoff = 0.5*(cos(pi*dr/6)+1) * (dr < 6): exactly zero beyond 6 -> no contribution
    if (dr >= 6.0f) return;

    int ai = nbr[e];
    int aj = nbr[N_EDGES + e];

    float inv = 1.0f / (dr + 1e-5f);
    float dx = x * inv, dy = y * inv, dz = z * inv;

    const float BETTA    = 49.0f / 36.0f;          // N_BASIS^2 / R_MAX^2
    const float RAD_NORM = 0.8981114f;             // (2*betta/pi)^0.75
    const float PI_OVER_6 = 0.52359877559f;
    const float INV_SQRT7 = 0.37796447301f;

    float cut = 0.5f * (__cosf(dr * PI_OVER_6) + 1.0f);
    float scale = cut * INV_SQRT7;

    float bas[7];
    #pragma unroll
    for (int b = 0; b < 7; b++) {
        float d = dr - (float)b;                   // shifts = 0,1,...,6
        bas[b] = RAD_NORM * __expf(-BETTA * d * d);
    }

    const float* c = coeffs + (Z[ai] * 119 + Z[aj]) * 35;
    float rad[5];
    #pragma unroll
    for (int r = 0; r < 5; r++) {
        float s = 0.0f;
        #pragma unroll
        for (int b = 0; b < 7; b++) s += c[r*7 + b] * bas[b];
        rad[r] = s * scale;
    }

    // unique moment basis: 1, dn(3), sym2(6), sym3(10)
    float Tu[20];
    Tu[0] = 1.0f;
    Tu[1] = dx; Tu[2] = dy; Tu[3] = dz;
    Tu[4] = dx*dx; Tu[5] = dx*dy; Tu[6] = dx*dz;
    Tu[7] = dy*dy; Tu[8] = dy*dz; Tu[9] = dz*dz;
    Tu[10] = Tu[4]*dx;  // 000
    Tu[11] = Tu[4]*dy;  // 001
    Tu[12] = Tu[4]*dz;  // 002
    Tu[13] = Tu[7]*dx;  // 011
    Tu[14] = Tu[5]*dz;  // 012
    Tu[15] = Tu[9]*dx;  // 022
    Tu[16] = Tu[7]*dy;  // 111
    Tu[17] = Tu[7]*dz;  // 112
    Tu[18] = Tu[9]*dy;  // 122
    Tu[19] = Tu[9]*dz;  // 222

    float* dst = g_mom + aj * MOM_PER_ATOM;
    #pragma unroll
    for (int r = 0; r < 5; r++) {
        float rv = rad[r];
        #pragma unroll
        for (int u = 0; u < 20; u++) {
            atomicAdd(dst + r*20 + u, rv * Tu[u]);
        }
    }
}

// One warp per atom. Stages symmetric-expanded moments + intermediates in SMEM,
// then computes all 355 non-trivial features and writes them through the
// reference's flat-reinterpret permutation: value at (feature f, atom a) lands
// at out[((f*A + a)/W)*360 + off + (f*A + a)%W].
__global__ void __launch_bounds__(256) contract_kernel(float* __restrict__ out)
{
    __shared__ float sm[8][540];
    int warp = threadIdx.x >> 5;
    int lane = threadIdx.x & 31;
    int a = blockIdx.x * 8 + warp;
    if (a >= N_ATOMS) return;

    float* M1  = sm[warp];        // 15  : m1[r][i]
    float* M2F = M1 + 15;         // 45  : m2[r][3i+j] (expanded)
    float* M3F = M2F + 45;        // 135 : m3[r][9i+3j+k] (expanded)
    float* C4  = M3F + 135;       // 135 : C4[p][3j+k] = sum_i m2[r,i,j]m2[s,i,k]
    float* C6  = C4 + 135;        // 135 : C6[p][3k+l] = sum_ij m3[r,i,j,k]m3[s,i,j,l]
    float* E7  = C6 + 135;        // 75  : E7[r*5+s][k] = sum_ij m3[r,i,j,k]m2[s,i,j]

    const float* mom = g_mom + a * MOM_PER_ATOM;

    // Stage A: expansion (200 items) + m0 direct output (contr_0 is untransposed)
    for (int it = lane; it < 200; it += 32) {
        if (it < 5) {
            out[a * 360 + it] = mom[it * 20];
        } else if (it < 20) {
            int t = it - 5; int r = t / 3, i = t % 3;
            M1[t] = mom[r*20 + 1 + i];
        } else if (it < 65) {
            int t = it - 20; int r = t / 9, u = t % 9;
            M2F[t] = mom[r*20 + 4 + c_F2U[u]];
        } else {
            int t = it - 65; int r = t / 27, u = t % 27;
            M3F[t] = mom[r*20 + 10 + c_F3U[u]];
        }
    }
    __syncwarp();

    // Stage B: intermediates (345 items)
    for (int it = lane; it < 345; it += 32) {
        if (it < 135) {
            int p = it / 9, jk = it % 9; int j = jk / 3, k = jk % 3;
            int r = c_T2I[p], s = c_T2J[p];
            float v = 0.0f;
            #pragma unroll
            for (int i = 0; i < 3; i++)
                v += M2F[r*9 + i*3 + j] * M2F[s*9 + i*3 + k];
            C4[it] = v;
        } else if (it < 270) {
            int t = it - 135; int p = t / 9, kl = t % 9; int k = kl / 3, l = kl % 3;
            int r = c_T2I[p], s = c_T2J[p];
            float v = 0.0f;
            #pragma unroll
            for (int m = 0; m < 9; m++)
                v += M3F[r*27 + 3*m + k] * M3F[s*27 + 3*m + l];
            C6[t] = v;
        } else {
            int t = it - 270; int rs = t / 3, k = t % 3; int r = rs / 5, s = rs % 5;
            float v = 0.0f;
            #pragma unroll
            for (int m = 0; m < 9; m++)
                v += M3F[r*27 + 3*m + k] * M2F[s*9 + m];
            E7[t] = v;
        }
    }
    __syncwarp();

    // Stage C: 355 features across 7 blocks (each block: F features == W cols)
    for (int it = lane; it < 355; it += 32) {
        float v = 0.0f;
        int off, W, f;
        if (it < 15) {                       // contr_1
            int p = it; int r = c_T2I[p], s = c_T2J[p];
            #pragma unroll
            for (int i = 0; i < 3; i++) v += M1[r*3+i] * M1[s*3+i];
            off = 5; W = 15; f = p;
        } else if (it < 30) {                // contr_2
            int p = it - 15; int r = c_T2I[p], s = c_T2J[p];
            #pragma unroll
            for (int u = 0; u < 9; u++) v += M2F[r*9+u] * M2F[s*9+u];
            off = 20; W = 15; f = p;
        } else if (it < 45) {                // contr_3
            int p = it - 30; int r = c_T2I[p], s = c_T2J[p];
            #pragma unroll
            for (int u = 0; u < 27; u++) v += M3F[r*27+u] * M3F[s*27+u];
            off = 35; W = 15; f = p;
        } else if (it < 80) {                // contr_4
            int q = it - 45;
            int r = c_T3I[q], s = c_T3J[q], t = c_T3K[q];
            int p = r*(r+1)/2 + s;
            #pragma unroll
            for (int u = 0; u < 9; u++) v += C4[p*9+u] * M2F[t*9+u];
            off = 50; W = 35; f = q;
        } else if (it < 155) {               // contr_5
            int loc = it - 80; int p = loc / 5, t = loc % 5;
            int r = c_T2I[p], s = c_T2J[p];
            #pragma unroll
            for (int i = 0; i < 3; i++) {
                float m1ri = M1[r*3+i];
                #pragma unroll
                for (int j = 0; j < 3; j++)
                    v += m1ri * M1[s*3+j] * M2F[t*9 + 3*i + j];
            }
            off = 85; W = 75; f = loc;
        } else if (it < 230) {               // contr_6
            int loc = it - 155; int p = loc / 5, t = loc % 5;
            #pragma unroll
            for (int u = 0; u < 9; u++) v += C6[p*9+u] * M2F[t*9+u];
            off = 160; W = 75; f = loc;
        } else {                             // contr_7
            int loc = it - 230;
            int r = loc / 25, s = (loc / 5) % 5, t = loc % 5;
            #pragma unroll
            for (int k = 0; k < 3; k++) v += E7[(r*5+s)*3 + k] * M1[t*3+k];
            off = 235; W = 125; f = loc;
        }
        // flat-reinterpret permutation: (f, a) in (F, A) C-order -> (A, W) row-major
        int idx = f * N_ATOMS + a;
        int ao = idx / W;
        int cc = idx - ao * W;
        out[ao * 360 + off + cc] = v;
    }
}

extern "C" void kernel_launch(void* const* d_in, const int* in_sizes, int n_in,
                              void* d_out, int out_size)
{
    const float* dr_vec = (const float*)d_in[0];
    const int*   Z      = (const int*)d_in[1];
    const int*   nbr    = (const int*)d_in[2];
    const float* coeffs = (const float*)d_in[3];
    float* out = (float*)d_out;

    (void)in_sizes; (void)n_in; (void)out_size;

    zero_kernel<<<(N_ATOMS * MOM_PER_ATOM + 255) / 256, 256>>>();
    edge_kernel<<<(N_EDGES + 255) / 256, 256>>>(dr_vec, Z, nbr, coeffs);
    contract_kernel<<<(N_ATOMS + 7) / 8, 256>>>(out);
}

// round 7
// speedup vs baseline: 2.5714x; 2.5714x over previous
#include <cuda_runtime.h>

#define N_ATOMS 25000
#define N_EDGES 1000000
// moments per atom: 5 radial * 20 unique (1 + 3 + 6 + 10)
#define MOM_PER_ATOM 100

__device__ __align__(16) float g_mom[N_ATOMS * MOM_PER_ATOM];

// tril2 pairs (r>=s), order: for r in 0..4 for s in 0..r
static __device__ const int c_T2I[15] = {0,1,1,2,2,2,3,3,3,3,4,4,4,4,4};
static __device__ const int c_T2J[15] = {0,0,1,0,1,2,0,1,2,3,0,1,2,3,4};
// tril3 triples (r>=s>=t)
static __device__ const int c_T3I[35] = {0, 1,1,1, 2,2,2,2,2,2, 3,3,3,3,3,3,3,3,3,3,
                                         4,4,4,4,4,4,4,4,4,4,4,4,4,4,4};
static __device__ const int c_T3J[35] = {0, 0,1,1, 0,1,1,2,2,2, 0,1,1,2,2,2,3,3,3,3,
                                         0,1,1,2,2,2,3,3,3,3,4,4,4,4,4};
static __device__ const int c_T3K[35] = {0, 0,0,1, 0,0,1,0,1,2, 0,0,1,0,1,2,0,1,2,3,
                                         0,0,1,0,1,2,0,1,2,3,0,1,2,3,4};
// full (i,j) -> unique symmetric index (pairs ordered 00,01,02,11,12,22)
static __device__ const int c_F2U[9]  = {0,1,2, 1,3,4, 2,4,5};
// full (i,j,k) -> unique (triples ordered 000,001,002,011,012,022,111,112,122,222)
static __device__ const int c_F3U[27] = {0,1,2, 1,3,4, 2,4,5,
                                         1,3,4, 3,6,7, 4,7,8,
                                         2,4,5, 4,7,8, 5,8,9};

__global__ void zero_kernel() {
    int t = blockIdx.x * blockDim.x + threadIdx.x;
    float4* p = reinterpret_cast<float4*>(g_mom);
    if (t < (N_ATOMS * MOM_PER_ATOM) / 4)
        p[t] = make_float4(0.f, 0.f, 0.f, 0.f);
}

__device__ __forceinline__ void red_v4(float* addr, float a, float b, float c, float d) {
    asm volatile("red.global.add.v4.f32 [%0], {%1, %2, %3, %4};"
                 :: "l"(addr), "f"(a), "f"(b), "f"(c), "f"(d) : "memory");
}

__global__ void __launch_bounds__(256) edge_kernel(
    const float* __restrict__ dr_vec,
    const int*   __restrict__ Z,
    const int*   __restrict__ nbr,
    const float* __restrict__ coeffs)
{
    int e = blockIdx.x * blockDim.x + threadIdx.x;
    if (e >= N_EDGES) return;

    float x = dr_vec[3*e + 0];
    float y = dr_vec[3*e + 1];
    float z = dr_vec[3*e + 2];
    float dr = sqrtf(x*x + y*y + z*z);
    // cutoff = 0.5*(cos(pi*dr/6)+1) * (dr < 6): exactly zero beyond 6 -> no contribution
    if (dr >= 6.0f) return;

    int ai = nbr[e];
    int aj = nbr[N_EDGES + e];

    float inv = 1.0f / (dr + 1e-5f);
    float dx = x * inv, dy = y * inv, dz = z * inv;

    const float BETTA    = 49.0f / 36.0f;          // N_BASIS^2 / R_MAX^2
    const float RAD_NORM = 0.8981114f;             // (2*betta/pi)^0.75
    const float PI_OVER_6 = 0.52359877559f;
    const float INV_SQRT7 = 0.37796447301f;

    float cut = 0.5f * (__cosf(dr * PI_OVER_6) + 1.0f);
    float scale = cut * INV_SQRT7;

    float bas[7];
    #pragma unroll
    for (int b = 0; b < 7; b++) {
        float d = dr - (float)b;                   // shifts = 0,1,...,6
        bas[b] = RAD_NORM * __expf(-BETTA * d * d);
    }

    const float* c = coeffs + (Z[ai] * 119 + Z[aj]) * 35;
    float rad[5];
    #pragma unroll
    for (int r = 0; r < 5; r++) {
        float s = 0.0f;
        #pragma unroll
        for (int b = 0; b < 7; b++) s += c[r*7 + b] * bas[b];
        rad[r] = s * scale;
    }

    // unique moment basis: 1, dn(3), sym2(6), sym3(10)
    float Tu[20];
    Tu[0] = 1.0f;
    Tu[1] = dx; Tu[2] = dy; Tu[3] = dz;
    Tu[4] = dx*dx; Tu[5] = dx*dy; Tu[6] = dx*dz;
    Tu[7] = dy*dy; Tu[8] = dy*dz; Tu[9] = dz*dz;
    Tu[10] = Tu[4]*dx;  // 000
    Tu[11] = Tu[4]*dy;  // 001
    Tu[12] = Tu[4]*dz;  // 002
    Tu[13] = Tu[7]*dx;  // 011
    Tu[14] = Tu[5]*dz;  // 012
    Tu[15] = Tu[9]*dx;  // 022
    Tu[16] = Tu[7]*dy;  // 111
    Tu[17] = Tu[7]*dz;  // 112
    Tu[18] = Tu[9]*dy;  // 122
    Tu[19] = Tu[9]*dz;  // 222

    float* dst = g_mom + aj * MOM_PER_ATOM;
    // 25 vectorized 128-bit REDs instead of 100 scalar REDs.
    // Each r-block is 20 floats = 5 aligned float4 groups (base 16B-aligned).
    #pragma unroll
    for (int r = 0; r < 5; r++) {
        float rv = rad[r];
        float* d0 = dst + r * 20;
        #pragma unroll
        for (int g = 0; g < 5; g++) {
            red_v4(d0 + 4*g,
                   rv * Tu[4*g + 0], rv * Tu[4*g + 1],
                   rv * Tu[4*g + 2], rv * Tu[4*g + 3]);
        }
    }
}

// One warp per atom. Stages symmetric-expanded moments + intermediates in SMEM,
// then computes all 355 non-trivial features and writes them through the
// reference's flat-reinterpret permutation: value at (feature f, atom a) lands
// at out[((f*A + a)/W)*360 + off + (f*A + a)%W].
__global__ void __launch_bounds__(256) contract_kernel(float* __restrict__ out)
{
    __shared__ float sm[8][540];
    int warp = threadIdx.x >> 5;
    int lane = threadIdx.x & 31;
    int a = blockIdx.x * 8 + warp;
    if (a >= N_ATOMS) return;

    float* M1  = sm[warp];        // 15  : m1[r][i]
    float* M2F = M1 + 15;         // 45  : m2[r][3i+j] (expanded)
    float* M3F = M2F + 45;        // 135 : m3[r][9i+3j+k] (expanded)
    float* C4  = M3F + 135;       // 135 : C4[p][3j+k] = sum_i m2[r,i,j]m2[s,i,k]
    float* C6  = C4 + 135;        // 135 : C6[p][3k+l] = sum_ij m3[r,i,j,k]m3[s,i,j,l]
    float* E7  = C6 + 135;        // 75  : E7[r*5+s][k] = sum_ij m3[r,i,j,k]m2[s,i,j]

    const float* mom = g_mom + a * MOM_PER_ATOM;

    // Stage A: expansion (200 items) + m0 direct output (contr_0 is untransposed)
    for (int it = lane; it < 200; it += 32) {
        if (it < 5) {
            out[a * 360 + it] = mom[it * 20];
        } else if (it < 20) {
            int t = it - 5; int r = t / 3, i = t % 3;
            M1[t] = mom[r*20 + 1 + i];
        } else if (it < 65) {
            int t = it - 20; int r = t / 9, u = t % 9;
            M2F[t] = mom[r*20 + 4 + c_F2U[u]];
        } else {
            int t = it - 65; int r = t / 27, u = t % 27;
            M3F[t] = mom[r*20 + 10 + c_F3U[u]];
        }
    }
    __syncwarp();

    // Stage B: intermediates (345 items)
    for (int it = lane; it < 345; it += 32) {
        if (it < 135) {
            int p = it / 9, jk = it % 9; int j = jk / 3, k = jk % 3;
            int r = c_T2I[p], s = c_T2J[p];
            float v = 0.0f;
            #pragma unroll
            for (int i = 0; i < 3; i++)
                v += M2F[r*9 + i*3 + j] * M2F[s*9 + i*3 + k];
            C4[it] = v;
        } else if (it < 270) {
            int t = it - 135; int p = t / 9, kl = t % 9; int k = kl / 3, l = kl % 3;
            int r = c_T2I[p], s = c_T2J[p];
            float v = 0.0f;
            #pragma unroll
            for (int m = 0; m < 9; m++)
                v += M3F[r*27 + 3*m + k] * M3F[s*27 + 3*m + l];
            C6[t] = v;
        } else {
            int t = it - 270; int rs = t / 3, k = t % 3; int r = rs / 5, s = rs % 5;
            float v = 0.0f;
            #pragma unroll
            for (int m = 0; m < 9; m++)
                v += M3F[r*27 + 3*m + k] * M2F[s*9 + m];
            E7[t] = v;
        }
    }
    __syncwarp();

    // Stage C: 355 features across 7 blocks (each block: F features == W cols)
    for (int it = lane; it < 355; it += 32) {
        float v = 0.0f;
        int off, W, f;
        if (it < 15) {                       // contr_1
            int p = it; int r = c_T2I[p], s = c_T2J[p];
            #pragma unroll
            for (int i = 0; i < 3; i++) v += M1[r*3+i] * M1[s*3+i];
            off = 5; W = 15; f = p;
        } else if (it < 30) {                // contr_2
            int p = it - 15; int r = c_T2I[p], s = c_T2J[p];
            #pragma unroll
            for (int u = 0; u < 9; u++) v += M2F[r*9+u] * M2F[s*9+u];
            off = 20; W = 15; f = p;
        } else if (it < 45) {                // contr_3
            int p = it - 30; int r = c_T2I[p], s = c_T2J[p];
            #pragma unroll
            for (int u = 0; u < 27; u++) v += M3F[r*27+u] * M3F[s*27+u];
            off = 35; W = 15; f = p;
        } else if (it < 80) {                // contr_4
            int q = it - 45;
            int r = c_T3I[q], s = c_T3J[q], t = c_T3K[q];
            int p = r*(r+1)/2 + s;
            #pragma unroll
            for (int u = 0; u < 9; u++) v += C4[p*9+u] * M2F[t*9+u];
            off = 50; W = 35; f = q;
        } else if (it < 155) {               // contr_5
            int loc = it - 80; int p = loc / 5, t = loc % 5;
            int r = c_T2I[p], s = c_T2J[p];
            #pragma unroll
            for (int i = 0; i < 3; i++) {
                float m1ri = M1[r*3+i];
                #pragma unroll
                for (int j = 0; j < 3; j++)
                    v += m1ri * M1[s*3+j] * M2F[t*9 + 3*i + j];
            }
            off = 85; W = 75; f = loc;
        } else if (it < 230) {               // contr_6
            int loc = it - 155; int p = loc / 5, t = loc % 5;
            #pragma unroll
            for (int u = 0; u < 9; u++) v += C6[p*9+u] * M2F[t*9+u];
            off = 160; W = 75; f = loc;
        } else {                             // contr_7
            int loc = it - 230;
            int r = loc / 25, s = (loc / 5) % 5, t = loc % 5;
            #pragma unroll
            for (int k = 0; k < 3; k++) v += E7[(r*5+s)*3 + k] * M1[t*3+k];
            off = 235; W = 125; f = loc;
        }
        // flat-reinterpret permutation: (f, a) in (F, A) C-order -> (A, W) row-major
        int idx = f * N_ATOMS + a;
        int ao = idx / W;
        int cc = idx - ao * W;
        out[ao * 360 + off + cc] = v;
    }
}

extern "C" void kernel_launch(void* const* d_in, const int* in_sizes, int n_in,
                              void* d_out, int out_size)
{
    const float* dr_vec = (const float*)d_in[0];
    const int*   Z      = (const int*)d_in[1];
    const int*   nbr    = (const int*)d_in[2];
    const float* coeffs = (const float*)d_in[3];
    float* out = (float*)d_out;

    (void)in_sizes; (void)n_in; (void)out_size;

    zero_kernel<<<(N_ATOMS * MOM_PER_ATOM / 4 + 255) / 256, 256>>>();
    edge_kernel<<<(N_EDGES + 255) / 256, 256>>>(dr_vec, Z, nbr, coeffs);
    contract_kernel<<<(N_ATOMS + 7) / 8, 256>>>(out);
}